// round 1
// baseline (speedup 1.0000x reference)
#include <cuda_runtime.h>

// Problem dims (fixed by reference)
#define UDIM 400
#define VDIM 400
#define MDIM 4
#define NTEX (MDIM * UDIM * VDIM)   // 640,000 texels

// Packed table: per texel 12 floats = [W00..W22 (row-major 3x3), B0,B1,B2]
// 48 bytes per record, 16B-aligned -> every record covers exactly 2 L2 sectors.
__device__ __align__(16) float g_packed[(size_t)NTEX * 12];

__global__ void pack_kernel(const float* __restrict__ m_param,
                            const float* __restrict__ b_param) {
    int t = blockIdx.x * blockDim.x + threadIdx.x;
    if (t >= NTEX) return;
    const float* w = m_param + (size_t)t * 9;
    const float* b = b_param + (size_t)t * 3;
    float4 r0 = make_float4(w[0], w[1], w[2], w[3]);
    float4 r1 = make_float4(w[4], w[5], w[6], w[7]);
    float4 r2 = make_float4(w[8], b[0], b[1], b[2]);
    float4* dst = reinterpret_cast<float4*>(g_packed + (size_t)t * 12);
    dst[0] = r0; dst[1] = r1; dst[2] = r2;
}

__device__ __forceinline__ void accum_corner(const float4* __restrict__ tbl,
                                             int rec, float w, float acc[12]) {
    // rec is texel index; record = 3 consecutive float4
    const float4* p = tbl + (size_t)rec * 3;
    float4 a = __ldg(p + 0);
    float4 b = __ldg(p + 1);
    float4 c = __ldg(p + 2);
    acc[0]  = fmaf(w, a.x, acc[0]);
    acc[1]  = fmaf(w, a.y, acc[1]);
    acc[2]  = fmaf(w, a.z, acc[2]);
    acc[3]  = fmaf(w, a.w, acc[3]);
    acc[4]  = fmaf(w, b.x, acc[4]);
    acc[5]  = fmaf(w, b.y, acc[5]);
    acc[6]  = fmaf(w, b.z, acc[6]);
    acc[7]  = fmaf(w, b.w, acc[7]);
    acc[8]  = fmaf(w, c.x, acc[8]);
    acc[9]  = fmaf(w, c.y, acc[9]);
    acc[10] = fmaf(w, c.z, acc[10]);
    acc[11] = fmaf(w, c.w, acc[11]);
}

__global__ __launch_bounds__(256) void interp_kernel(
    const float* __restrict__ x,
    const int*   __restrict__ m,
    const float* __restrict__ u,
    const float* __restrict__ v,
    float* __restrict__ out,
    int N)
{
    int tid = blockIdx.x * blockDim.x + threadIdx.x;
    if (tid >= N) return;

    // --- index math (mirrors reference exactly) ---
    float iu = u[tid] * (float)UDIM;
    float iv = v[tid] * (float)VDIM;
    if (iu == (float)UDIM) iu = (float)(UDIM - 1);
    if (iv == (float)VDIM) iv = (float)(VDIM - 1);

    float i1f = floorf(iu);
    float j1f = floorf(iv);
    int i1 = (int)i1f;
    int j1 = (int)j1f;
    int i2 = i1 + 1; if (i2 == UDIM) i2 = 0;
    int j2 = j1 + 1; if (j2 == VDIM) j2 = 0;
    float ir = iu - i1f;
    float jr = iv - j1f;

    int mm = m[tid];
    int base = mm * (UDIM * VDIM);
    int r11 = base + i1 * VDIM + j1;   // (i1, j1)
    int r21 = base + i2 * VDIM + j1;   // (i2, j1)
    int r12 = base + i1 * VDIM + j2;   // (i1, j2)
    int r22 = base + i2 * VDIM + j2;   // (i2, j2)

    float w11 = (1.0f - ir) * (1.0f - jr);
    float w21 = ir * (1.0f - jr);
    float w12 = (1.0f - ir) * jr;
    float w22 = ir * jr;

    const float4* tbl = reinterpret_cast<const float4*>(g_packed);

    float acc[12];
    #pragma unroll
    for (int k = 0; k < 12; k++) acc[k] = 0.0f;

    accum_corner(tbl, r11, w11, acc);
    accum_corner(tbl, r21, w21, acc);
    accum_corner(tbl, r12, w12, acc);
    accum_corner(tbl, r22, w22, acc);

    // out_j = sum_i x_i * W[i][j] + B[j]   (W row-major in acc[0..8], B in acc[9..11])
    float x0 = x[3 * tid + 0];
    float x1 = x[3 * tid + 1];
    float x2 = x[3 * tid + 2];

    out[3 * tid + 0] = fmaf(x0, acc[0], fmaf(x1, acc[3], fmaf(x2, acc[6], acc[9])));
    out[3 * tid + 1] = fmaf(x0, acc[1], fmaf(x1, acc[4], fmaf(x2, acc[7], acc[10])));
    out[3 * tid + 2] = fmaf(x0, acc[2], fmaf(x1, acc[5], fmaf(x2, acc[8], acc[11])));
}

extern "C" void kernel_launch(void* const* d_in, const int* in_sizes, int n_in,
                              void* d_out, int out_size) {
    const float* x       = (const float*)d_in[0];   // [N,3]
    const int*   m       = (const int*)  d_in[1];   // [N]
    const float* u       = (const float*)d_in[2];   // [N]
    const float* v       = (const float*)d_in[3];   // [N]
    const float* m_param = (const float*)d_in[4];   // [M,U*V,3,3]
    const float* b_param = (const float*)d_in[5];   // [M,U*V,1,3]
    float* out = (float*)d_out;

    int N = in_sizes[1];  // element count of m

    // Stage 1: repack table into 48B aligned records (deterministic, every call)
    {
        int threads = 256;
        int blocks = (NTEX + threads - 1) / threads;
        pack_kernel<<<blocks, threads>>>(m_param, b_param);
    }
    // Stage 2: gather + interp + matvec
    {
        int threads = 256;
        int blocks = (N + threads - 1) / threads;
        interp_kernel<<<blocks, threads>>>(x, m, u, v, out, N);
    }
}

// round 2
// speedup vs baseline: 1.0175x; 1.0175x over previous
#include <cuda_runtime.h>

// Problem dims (fixed by reference)
#define UDIM 400
#define VDIM 400
#define MDIM 4
#define VPAD (VDIM + 1)                    // duplicate column 0 at j=400 -> no j-wrap
#define NTEXP (MDIM * UDIM * VPAD)          // 641,600 padded texels

// Packed table: per texel 12 floats = [W00..W22 (row-major 3x3), B0,B1,B2]
// 48 bytes per record, j-contiguous. A (j1, j1+1) pair is 96B contiguous.
__device__ __align__(16) float g_packed[(size_t)NTEXP * 12];

__global__ __launch_bounds__(256) void pack_kernel(
    const float* __restrict__ m_param,
    const float* __restrict__ b_param)
{
    int t = blockIdx.x * blockDim.x + threadIdx.x;
    if (t >= NTEXP) return;
    int m  = t / (UDIM * VPAD);
    int r  = t % (UDIM * VPAD);
    int i  = r / VPAD;
    int jp = r % VPAD;
    int j  = (jp == VDIM) ? 0 : jp;          // padded column duplicates j=0
    int src = (m * UDIM + i) * VDIM + j;

    const float* w = m_param + (size_t)src * 9;
    const float* b = b_param + (size_t)src * 3;
    float4 r0 = make_float4(w[0], w[1], w[2], w[3]);
    float4 r1 = make_float4(w[4], w[5], w[6], w[7]);
    float4 r2 = make_float4(w[8], b[0], b[1], b[2]);
    float4* dst = reinterpret_cast<float4*>(g_packed + (size_t)t * 12);
    dst[0] = r0; dst[1] = r1; dst[2] = r2;
}

__device__ __forceinline__ void accum_rec(const float4* __restrict__ p,
                                          float w, float acc[12]) {
    float4 a = __ldg(p + 0);
    float4 b = __ldg(p + 1);
    float4 c = __ldg(p + 2);
    acc[0]  = fmaf(w, a.x, acc[0]);
    acc[1]  = fmaf(w, a.y, acc[1]);
    acc[2]  = fmaf(w, a.z, acc[2]);
    acc[3]  = fmaf(w, a.w, acc[3]);
    acc[4]  = fmaf(w, b.x, acc[4]);
    acc[5]  = fmaf(w, b.y, acc[5]);
    acc[6]  = fmaf(w, b.z, acc[6]);
    acc[7]  = fmaf(w, b.w, acc[7]);
    acc[8]  = fmaf(w, c.x, acc[8]);
    acc[9]  = fmaf(w, c.y, acc[9]);
    acc[10] = fmaf(w, c.z, acc[10]);
    acc[11] = fmaf(w, c.w, acc[11]);
}

__global__ __launch_bounds__(256) void interp_kernel(
    const float* __restrict__ x,
    const int*   __restrict__ m,
    const float* __restrict__ u,
    const float* __restrict__ v,
    float* __restrict__ out,
    int N)
{
    int tid = blockIdx.x * blockDim.x + threadIdx.x;
    if (tid >= N) return;

    // --- index math (mirrors reference exactly) ---
    float iu = u[tid] * (float)UDIM;
    float iv = v[tid] * (float)VDIM;
    if (iu == (float)UDIM) iu = (float)(UDIM - 1);
    if (iv == (float)VDIM) iv = (float)(VDIM - 1);

    float i1f = floorf(iu);
    float j1f = floorf(iv);
    int i1 = (int)i1f;
    int j1 = (int)j1f;                       // 0..399; j2 = j1+1 via padded column
    int i2 = i1 + 1; if (i2 == UDIM) i2 = 0; // i wraps; j wrap absorbed by padding
    float ir = iu - i1f;
    float jr = iv - j1f;

    int mm = m[tid];
    int rowA = (mm * UDIM + i1) * VPAD + j1; // record index of (i1, j1); (i1,j1+1) adjacent
    int rowB = (mm * UDIM + i2) * VPAD + j1;

    float wA1 = (1.0f - ir) * (1.0f - jr);
    float wA2 = (1.0f - ir) * jr;
    float wB1 = ir * (1.0f - jr);
    float wB2 = ir * jr;

    const float4* tbl = reinterpret_cast<const float4*>(g_packed);
    const float4* pA = tbl + (size_t)rowA * 3;  // 6 consecutive float4 (96B)
    const float4* pB = tbl + (size_t)rowB * 3;  // 6 consecutive float4 (96B)

    float acc[12];
    #pragma unroll
    for (int k = 0; k < 12; k++) acc[k] = 0.0f;

    accum_rec(pA + 0, wA1, acc);   // (i1, j1)
    accum_rec(pA + 3, wA2, acc);   // (i1, j1+1)
    accum_rec(pB + 0, wB1, acc);   // (i2, j1)
    accum_rec(pB + 3, wB2, acc);   // (i2, j1+1)

    // out_j = sum_i x_i * W[i][j] + B[j]   (W row-major in acc[0..8], B in acc[9..11])
    float x0 = x[3 * tid + 0];
    float x1 = x[3 * tid + 1];
    float x2 = x[3 * tid + 2];

    out[3 * tid + 0] = fmaf(x0, acc[0], fmaf(x1, acc[3], fmaf(x2, acc[6], acc[9])));
    out[3 * tid + 1] = fmaf(x0, acc[1], fmaf(x1, acc[4], fmaf(x2, acc[7], acc[10])));
    out[3 * tid + 2] = fmaf(x0, acc[2], fmaf(x1, acc[5], fmaf(x2, acc[8], acc[11])));
}

extern "C" void kernel_launch(void* const* d_in, const int* in_sizes, int n_in,
                              void* d_out, int out_size) {
    const float* x       = (const float*)d_in[0];   // [N,3]
    const int*   m       = (const int*)  d_in[1];   // [N]
    const float* u       = (const float*)d_in[2];   // [N]
    const float* v       = (const float*)d_in[3];   // [N]
    const float* m_param = (const float*)d_in[4];   // [M,U*V,3,3]
    const float* b_param = (const float*)d_in[5];   // [M,U*V,1,3]
    float* out = (float*)d_out;

    int N = in_sizes[1];  // element count of m

    // Stage 1: repack table (with duplicated j=0 column) into 48B records
    {
        int threads = 256;
        int blocks = (NTEXP + threads - 1) / threads;
        pack_kernel<<<blocks, threads>>>(m_param, b_param);
    }
    // Stage 2: gather + interp + matvec
    {
        int threads = 256;
        int blocks = (N + threads - 1) / threads;
        interp_kernel<<<blocks, threads>>>(x, m, u, v, out, N);
    }
}